// round 14
// baseline (speedup 1.0000x reference)
#include <cuda_runtime.h>
#include <cuda_bf16.h>

#define Bsz   256
#define Tsz   512
#define Tpad  520
#define Csz   128
#define Lsz   64
#define BLANKC 127
#define PF    8
#define RW    34                 // row stride in u32 words (136 B)
#define LN2f  0.69314718055994530942f
#define ESENT (-(1 << 29))

// packed per-(b,t) row: words 0..31 = bf16x2(p_label(2l), p_label(2l+1));
// word 32 = f32 blank prob (bit pattern); word 33 = pad.
__device__ unsigned int g_pk[(size_t)Bsz * Tpad * RW];

// ---------------------------------------------------------------------------
// Kernel 1: softmax per (b,t) row; skip rows t >= input_length[b].
// ---------------------------------------------------------------------------
__global__ __launch_bounds__(128)
void ctc_probs(const float* __restrict__ y_pred,
               const int*   __restrict__ y_true,
               const int*   __restrict__ input_length) {
    const int row  = blockIdx.x * 4 + (threadIdx.x >> 5);   // row = b*512 + t
    const int lane = threadIdx.x & 31;
    const int wid  = (threadIdx.x >> 5);
    const int b = row >> 9;
    const int t = row & 511;
    if (t >= input_length[b]) return;                       // warp-uniform

    __shared__ __align__(16) float sh[4][128];

    const float4 v = reinterpret_cast<const float4*>(y_pred + (size_t)row * Csz)[lane];
    const float e0 = __expf(v.x), e1 = __expf(v.y),
                e2 = __expf(v.z), e3 = __expf(v.w);
    float esum = (e0 + e1) + (e2 + e3);
    #pragma unroll
    for (int o = 16; o; o >>= 1) esum += __shfl_xor_sync(0xffffffffu, esum, o);
    const float inv = __frcp_rn(esum);

    reinterpret_cast<float4*>(sh[wid])[lane] = make_float4(e0, e1, e2, e3);
    __syncwarp();

    const int* yt = y_true + b * Lsz;
    const float p1 = sh[wid][yt[2 * lane]]     * inv;
    const float p3 = sh[wid][yt[2 * lane + 1]] * inv;

    unsigned int* orow = g_pk + ((size_t)b * Tpad + t) * RW;
    const __nv_bfloat162 pk = __floats2bfloat162_rn(p1, p3);  // .x in low half
    orow[lane] = *reinterpret_cast<const unsigned int*>(&pk);
    if (lane == 0) orow[32] = __float_as_uint(sh[wid][BLANKC] * inv);
}

// renormalize v (>0) carrying exponent E -> mant in [1,2), int exp
__device__ __forceinline__ void norm2(float v, int E, float& m, int& e) {
    const int vb = __float_as_int(v);
    m = __int_as_float((vb & 0x007FFFFF) | 0x3F800000);
    e = E + (vb >> 23) - 127;
}
// exact 2^d for d <= 0: clamps to exactly 0 beyond -127
__device__ __forceinline__ float w2i(int d) {
    return __int_as_float(max(d + 127, 0) << 23);
}

// ---------------------------------------------------------------------------
// Kernel 2: forward-backward meet-in-the-middle. 4 batch rows per CTA,
// 8 warps: warp w -> row w>>1, dir w&1. SMSP w&3 hosts TWO independent
// chains (one fwd + one bwd) so their instructions interleave and fill
// each other's stall slots (R13 ran 1 warp/SMSP at only ~40% issue).
// Lane l owns states 4l..4l+3 (+state 128 as 5th scalar). Per-state int exp.
// ---------------------------------------------------------------------------
__global__ __launch_bounds__(256)
void ctc_ab(const int* __restrict__ y_true,
            const int* __restrict__ input_length,
            const int* __restrict__ label_length,
            float*     __restrict__ out) {
    const int l   = threadIdx.x & 31;
    const int wid = threadIdx.x >> 5;
    const int row = wid >> 1;               // batch row within CTA (0..3)
    const int dir = wid & 1;                // 0 = forward, 1 = backward
    const int b   = blockIdx.x * 4 + row;

    const int Trun  = input_length[b];
    const int Tlast = Trun - 1;
    const int tm    = Tlast >> 1;           // meeting time
    const int ll    = label_length[b];

    const int z1 = y_true[b * Lsz + 2 * l];
    const int z3 = y_true[b * Lsz + 2 * l + 1];
    const unsigned int* base = g_pk + (size_t)b * Tpad * RW;

    __shared__ __align__(16) float2 shB[4][132];

    float m0 = 1.f, m1 = 1.f, m2 = 1.f, m3 = 1.f, m4 = 1.f;
    int   e0 = ESENT, e1 = ESENT, e2 = ESENT, e3 = ESENT, e4 = ESENT;
    unsigned int xr[PF]; float pr[PF];

    if (dir == 0) {
        // ========================= FORWARD: t = 1..tm =========================
        const bool skip1 = (l > 0) && (z1 != y_true[b * Lsz + max(2 * l - 1, 0)]);
        const bool skip3 = (z3 != z1);

        if (l == 0) {                       // t=0 init (states 0,1)
            norm2(__uint_as_float(base[32]), 0, m0, e0);
            norm2(__int_as_float(base[0] << 16), 0, m1, e1);
        }
        #pragma unroll
        for (int i = 0; i < PF; ++i) {
            xr[i] = base[(1 + i) * RW + l];
            pr[i] = __uint_as_float(base[(1 + i) * RW + 32]);
        }
        const unsigned int* Pl = base + 9 * RW + l;
        const float*        Pb = reinterpret_cast<const float*>(base + 9 * RW + 32);

#define STEP_F(j) {                                                           \
    const unsigned int u = xr[j];                                             \
    const float pbv = pr[j];                                                  \
    xr[j] = Pl[(j) * RW];                                                     \
    pr[j] = Pb[(j) * RW];                                                     \
    const float p1v = __int_as_float(u << 16);                                \
    const float p3v = __int_as_float(u & 0xFFFF0000u);                        \
    float mN = __shfl_up_sync(0xffffffffu, m3, 1);                            \
    int   eN = __shfl_up_sync(0xffffffffu, e3, 1);                            \
    if (l == 0) { eN = ESENT; mN = 1.f; }                                     \
    float nm0, nm1, nm2, nm3, nm4; int ne0, ne1, ne2, ne3, ne4;               \
    { const int E = max(e0, eN);                                              \
      norm2((fmaf(mN, w2i(eN - E), m0 * w2i(e0 - E))) * pbv, E, nm0, ne0); }  \
    { const int ec = skip1 ? eN : ESENT;                                      \
      const int E = max(e1, max(e0, ec));                                     \
      float vv = fmaf(m0, w2i(e0 - E), m1 * w2i(e1 - E));                     \
      vv = fmaf(mN, w2i(ec - E), vv) * p1v;                                   \
      norm2(vv, E, nm1, ne1); }                                               \
    { const int E = max(e2, e1);                                              \
      norm2((fmaf(m1, w2i(e1 - E), m2 * w2i(e2 - E))) * pbv, E, nm2, ne2); }  \
    { const int ec = skip3 ? e1 : ESENT;                                      \
      const int E = max(e3, max(e2, ec));                                     \
      float vv = fmaf(m2, w2i(e2 - E), m3 * w2i(e3 - E));                     \
      vv = fmaf(m1, w2i(ec - E), vv) * p3v;                                   \
      norm2(vv, E, nm3, ne3); }                                               \
    { const int E = max(e4, e3);                                              \
      norm2((fmaf(m3, w2i(e3 - E), m4 * w2i(e4 - E))) * pbv, E, nm4, ne4); }  \
    m0 = nm0; e0 = ne0; m1 = nm1; e1 = ne1; m2 = nm2; e2 = ne2;               \
    m3 = nm3; e3 = ne3; m4 = nm4; e4 = ne4; }

        const int nsteps = tm;
        const int nfull  = nsteps >> 3;
        const int rem    = nsteps & 7;
        for (int c = 0; c < nfull; ++c) {
            #pragma unroll
            for (int j = 0; j < PF; ++j) STEP_F(j)
            Pl += PF * RW; Pb += PF * RW;
        }
        #pragma unroll
        for (int j = 0; j < PF; ++j) { if (j < rem) STEP_F(j) }
#undef STEP_F
    } else {
        // ================= BACKWARD: rows T_run-1 down to tm+1 =================
        const bool skipA = (z3 != z1);                               // 4l+1 -> 4l+3
        const bool skipB = (l < 31) && (y_true[b * Lsz + 2 * l + 2] != z3); // 4l+3 -> 4l+5
        float mz = 1.f; int ez;
        {   // init at t = T_run-1: indicator on states {2ll-1, 2ll}
            const int s0 = 4 * l, t1 = 2 * ll - 1, t2 = 2 * ll;
            e0 = (s0     == t1 || s0     == t2) ? 0 : ESENT;
            e1 = (s0 + 1 == t1 || s0 + 1 == t2) ? 0 : ESENT;
            e2 = (s0 + 2 == t1 || s0 + 2 == t2) ? 0 : ESENT;
            e3 = (s0 + 3 == t1 || s0 + 3 == t2) ? 0 : ESENT;
            ez = (ll == 64) ? 0 : ESENT;                  // state 128
        }
        #pragma unroll
        for (int i = 0; i < PF; ++i) {
            const int tt = Tlast - i;
            xr[i] = base[(size_t)tt * RW + l];
            pr[i] = __uint_as_float(base[(size_t)tt * RW + 32]);
        }
        const unsigned int* Pl = base + (size_t)(Tlast - 8) * RW + l;
        const float*        Pb = reinterpret_cast<const float*>(
                                     base + (size_t)(Tlast - 8) * RW + 32);

#define STEP_B(j) {                                                           \
    const unsigned int u = xr[j];                                             \
    const float pbv = pr[j];                                                  \
    xr[j] = Pl[-((j) * RW)];                                                  \
    pr[j] = Pb[-((j) * RW)];                                                  \
    const float p1v = __int_as_float(u << 16);                                \
    const float p3v = __int_as_float(u & 0xFFFF0000u);                        \
    const float g0 = m0 * pbv, g1 = m1 * p1v, g2 = m2 * pbv, g3 = m3 * p3v;   \
    const float gz = mz * pbv;                                                \
    float gA = __shfl_down_sync(0xffffffffu, g0, 1);                          \
    int   eA = __shfl_down_sync(0xffffffffu, e0, 1);                          \
    float gB = __shfl_down_sync(0xffffffffu, g1, 1);                          \
    int   eB = __shfl_down_sync(0xffffffffu, e1, 1);                          \
    if (l == 31) { gA = gz; eA = ez; gB = 1.f; eB = ESENT; }                  \
    float nm0, nm1, nm2, nm3; int ne0, ne1, ne2, ne3;                         \
    { const int E = max(e0, e1);                                              \
      norm2(fmaf(g1, w2i(e1 - E), g0 * w2i(e0 - E)), E, nm0, ne0); }          \
    { const int ec = skipA ? e3 : ESENT;                                      \
      const int E = max(e1, max(e2, ec));                                     \
      float vv = fmaf(g2, w2i(e2 - E), g1 * w2i(e1 - E));                     \
      vv = fmaf(g3, w2i(ec - E), vv);                                         \
      norm2(vv, E, nm1, ne1); }                                               \
    { const int E = max(e2, e3);                                              \
      norm2(fmaf(g3, w2i(e3 - E), g2 * w2i(e2 - E)), E, nm2, ne2); }          \
    { const int ec = skipB ? eB : ESENT;                                      \
      const int E = max(e3, max(eA, ec));                                     \
      float vv = fmaf(gA, w2i(eA - E), g3 * w2i(e3 - E));                     \
      vv = fmaf(gB, w2i(ec - E), vv);                                         \
      norm2(vv, E, nm3, ne3); }                                               \
    norm2(gz, ez, mz, ez);                                                    \
    m0 = nm0; e0 = ne0; m1 = nm1; e1 = ne1;                                   \
    m2 = nm2; e2 = ne2; m3 = nm3; e3 = ne3; }

        const int nsteps = Tlast - tm;
        const int nfull  = nsteps >> 3;
        const int rem    = nsteps & 7;
        for (int c = 0; c < nfull; ++c) {
            #pragma unroll
            for (int j = 0; j < PF; ++j) STEP_B(j)
            Pl -= PF * RW; Pb -= PF * RW;
        }
        #pragma unroll
        for (int j = 0; j < PF; ++j) { if (j < rem) STEP_B(j) }
#undef STEP_B

        shB[row][4 * l + 0] = make_float2(m0, __int_as_float(e0));
        shB[row][4 * l + 1] = make_float2(m1, __int_as_float(e1));
        shB[row][4 * l + 2] = make_float2(m2, __int_as_float(e2));
        shB[row][4 * l + 3] = make_float2(m3, __int_as_float(e3));
        if (l == 0) shB[row][128] = make_float2(mz, __int_as_float(ez));
    }

    __syncthreads();

    if (dir == 0) {
        // combine: p = sum_s alpha_tm(s) * beta_tm(s)
        const float2 b0 = shB[row][4 * l + 0];
        const float2 b1 = shB[row][4 * l + 1];
        const float2 b2 = shB[row][4 * l + 2];
        const float2 b3 = shB[row][4 * l + 3];
        const float pm0 = m0 * b0.x; const int pe0 = e0 + __float_as_int(b0.y);
        const float pm1 = m1 * b1.x; const int pe1 = e1 + __float_as_int(b1.y);
        const float pm2 = m2 * b2.x; const int pe2 = e2 + __float_as_int(b2.y);
        const float pm3 = m3 * b3.x; const int pe3 = e3 + __float_as_int(b3.y);
        float pm4 = 0.f; int pe4 = 2 * ESENT;
        if (l == 31) {
            const float2 bz = shB[row][128];
            pm4 = m4 * bz.x; pe4 = e4 + __float_as_int(bz.y);
        }
        int E = max(max(pe0, pe1), max(pe2, max(pe3, pe4)));
        #pragma unroll
        for (int o = 16; o; o >>= 1) E = max(E, __shfl_xor_sync(0xffffffffu, E, o));
        float v = pm0 * w2i(pe0 - E) + pm1 * w2i(pe1 - E)
                + pm2 * w2i(pe2 - E) + pm3 * w2i(pe3 - E)
                + pm4 * w2i(pe4 - E);
        #pragma unroll
        for (int o = 16; o; o >>= 1) v += __shfl_xor_sync(0xffffffffu, v, o);
        if (l == 0) out[b] = -(__logf(v) + (float)E * LN2f);
    }
}

// ---------------------------------------------------------------------------
extern "C" void kernel_launch(void* const* d_in, const int* in_sizes, int n_in,
                              void* d_out, int out_size) {
    const int*   y_true = nullptr;
    const float* y_pred = nullptr;
    const int*   ilen   = nullptr;
    const int*   llen   = nullptr;
    for (int i = 0; i < n_in; ++i) {
        const int sz = in_sizes[i];
        if (sz == Bsz * Tsz * Csz)      y_pred = (const float*)d_in[i];
        else if (sz == Bsz * Lsz)       y_true = (const int*)d_in[i];
        else if (sz == Bsz) {
            if (!ilen) ilen = (const int*)d_in[i];
            else       llen = (const int*)d_in[i];
        }
    }
    float* out = (float*)d_out;

    ctc_probs<<<(Bsz * Tsz) / 4, 128>>>(y_pred, y_true, ilen);
    ctc_ab<<<Bsz / 4, 256>>>(y_true, ilen, llen, out);
}

// round 15
// speedup vs baseline: 1.2394x; 1.2394x over previous
#include <cuda_runtime.h>
#include <cuda_bf16.h>

#define Bsz   256
#define Tsz   512
#define Tpad  520
#define Csz   128
#define Lsz   64
#define BLANKC 127
#define PF    8
#define RW    34                 // row stride in u32 words (136 B)
#define LN2f  0.69314718055994530942f
#define ESENT (-(1 << 29))

// packed per-(b,t) row: words 0..31 = bf16x2(p_label(2l), p_label(2l+1));
// word 32 = f32 blank prob (bit pattern); word 33 = pad.
__device__ unsigned int g_pk[(size_t)Bsz * Tpad * RW];

// ---------------------------------------------------------------------------
// Kernel 1: softmax per (b,t) row; skip rows t >= input_length[b].
// ---------------------------------------------------------------------------
__global__ __launch_bounds__(128)
void ctc_probs(const float* __restrict__ y_pred,
               const int*   __restrict__ y_true,
               const int*   __restrict__ input_length) {
    const int row  = blockIdx.x * 4 + (threadIdx.x >> 5);   // row = b*512 + t
    const int lane = threadIdx.x & 31;
    const int wid  = (threadIdx.x >> 5);
    const int b = row >> 9;
    const int t = row & 511;
    if (t >= input_length[b]) return;                       // warp-uniform

    __shared__ __align__(16) float sh[4][128];

    const float4 v = reinterpret_cast<const float4*>(y_pred + (size_t)row * Csz)[lane];
    const float e0 = __expf(v.x), e1 = __expf(v.y),
                e2 = __expf(v.z), e3 = __expf(v.w);
    float esum = (e0 + e1) + (e2 + e3);
    #pragma unroll
    for (int o = 16; o; o >>= 1) esum += __shfl_xor_sync(0xffffffffu, esum, o);
    const float inv = __frcp_rn(esum);

    reinterpret_cast<float4*>(sh[wid])[lane] = make_float4(e0, e1, e2, e3);
    __syncwarp();

    const int* yt = y_true + b * Lsz;
    const float p1 = sh[wid][yt[2 * lane]]     * inv;
    const float p3 = sh[wid][yt[2 * lane + 1]] * inv;

    unsigned int* orow = g_pk + ((size_t)b * Tpad + t) * RW;
    const __nv_bfloat162 pk = __floats2bfloat162_rn(p1, p3);  // .x in low half
    orow[lane] = *reinterpret_cast<const unsigned int*>(&pk);
    if (lane == 0) orow[32] = __float_as_uint(sh[wid][BLANKC] * inv);
}

// 2^d for d <= 0 via IMNMX (alu) + IMAD (fma pipe); exactly 0 for d <= -127
__device__ __forceinline__ float wexp(int d) {
    return __int_as_float(max(d, -127) * 8388608 + 0x3F800000);
}
// conditional renorm: DN=1 -> mant to [1,2), int exp; DN=0 -> keep split as-is
#define NRM(v, E, m, e, DN)                                                   \
    if (DN) { const int _vb = __float_as_int(v);                              \
        m = __int_as_float((_vb & 0x007FFFFF) | 0x3F800000);                  \
        e = (E) + (_vb >> 23) - 127; }                                        \
    else { m = (v); e = (E); }

// ---------------------------------------------------------------------------
// Kernel 2: forward-backward meet-in-the-middle (R13 layout: 2 rows/CTA,
// 4 warps = 1 chain per SMSP). Deferred renorm (every 4th step) + FMA-pipe
// weight construction to break the ALU-pipe rt=2 throughput floor.
// ---------------------------------------------------------------------------
__global__ __launch_bounds__(128)
void ctc_ab(const int* __restrict__ y_true,
            const int* __restrict__ input_length,
            const int* __restrict__ label_length,
            float*     __restrict__ out) {
    const int l   = threadIdx.x & 31;
    const int wid = threadIdx.x >> 5;
    const int row = wid >> 1;               // batch row within CTA
    const int dir = wid & 1;                // 0 = forward, 1 = backward
    const int b   = blockIdx.x * 2 + row;

    const int Trun  = input_length[b];
    const int Tlast = Trun - 1;
    const int tm    = Tlast >> 1;           // meeting time
    const int ll    = label_length[b];

    const int z1 = y_true[b * Lsz + 2 * l];
    const int z3 = y_true[b * Lsz + 2 * l + 1];
    const unsigned int* base = g_pk + (size_t)b * Tpad * RW;

    __shared__ __align__(16) float2 shB[2][132];

    float m0 = 1.f, m1 = 1.f, m2 = 1.f, m3 = 1.f, m4 = 1.f;
    int   e0 = ESENT, e1 = ESENT, e2 = ESENT, e3 = ESENT, e4 = ESENT;
    unsigned int xr[PF]; float pr[PF];

    if (dir == 0) {
        // ========================= FORWARD: t = 1..tm =========================
        const bool skip1 = (l > 0) && (z1 != y_true[b * Lsz + max(2 * l - 1, 0)]);
        const bool skip3 = (z3 != z1);

        if (l == 0) {                       // t=0 init (states 0,1)
            const int vb = __float_as_int(__uint_as_float(base[32]));
            m0 = __int_as_float((vb & 0x007FFFFF) | 0x3F800000);
            e0 = (vb >> 23) - 127;
            const int vb1 = __float_as_int(__int_as_float(base[0] << 16));
            m1 = __int_as_float((vb1 & 0x007FFFFF) | 0x3F800000);
            e1 = (vb1 >> 23) - 127;
        }
        #pragma unroll
        for (int i = 0; i < PF; ++i) {
            xr[i] = base[(1 + i) * RW + l];
            pr[i] = __uint_as_float(base[(1 + i) * RW + 32]);
        }
        const unsigned int* Pl = base + 9 * RW + l;
        const float*        Pb = reinterpret_cast<const float*>(base + 9 * RW + 32);

#define STEP_F(j, DN) {                                                       \
    const unsigned int u = xr[j];                                             \
    const float pbv = pr[j];                                                  \
    xr[j] = Pl[(j) * RW];                                                     \
    pr[j] = Pb[(j) * RW];                                                     \
    const float p1v = __int_as_float(u << 16);                                \
    const float p3v = __int_as_float(u & 0xFFFF0000u);                        \
    float mN = __shfl_up_sync(0xffffffffu, m3, 1);                            \
    int   eN = __shfl_up_sync(0xffffffffu, e3, 1);                            \
    if (l == 0) { eN = ESENT; mN = 1.f; }                                     \
    float nm0, nm1, nm2, nm3, nm4; int ne0, ne1, ne2, ne3, ne4;               \
    { const int E = max(e0, eN);                                              \
      const float vv = fmaf(mN, wexp(eN - E), m0 * wexp(e0 - E)) * pbv;       \
      NRM(vv, E, nm0, ne0, DN) }                                              \
    { const int ec = skip1 ? eN : ESENT;                                      \
      const int E = max(e1, max(e0, ec));                                     \
      float vv = fmaf(m0, wexp(e0 - E), m1 * wexp(e1 - E));                   \
      vv = fmaf(mN, wexp(ec - E), vv) * p1v;                                  \
      NRM(vv, E, nm1, ne1, DN) }                                              \
    { const int E = max(e2, e1);                                              \
      const float vv = fmaf(m1, wexp(e1 - E), m2 * wexp(e2 - E)) * pbv;       \
      NRM(vv, E, nm2, ne2, DN) }                                              \
    { const int ec = skip3 ? e1 : ESENT;                                      \
      const int E = max(e3, max(e2, ec));                                     \
      float vv = fmaf(m2, wexp(e2 - E), m3 * wexp(e3 - E));                   \
      vv = fmaf(m1, wexp(ec - E), vv) * p3v;                                  \
      NRM(vv, E, nm3, ne3, DN) }                                              \
    { const int E = max(e4, e3);                                              \
      const float vv = fmaf(m3, wexp(e3 - E), m4 * wexp(e4 - E)) * pbv;       \
      NRM(vv, E, nm4, ne4, DN) }                                              \
    m0 = nm0; e0 = ne0; m1 = nm1; e1 = ne1; m2 = nm2; e2 = ne2;               \
    m3 = nm3; e3 = ne3; m4 = nm4; e4 = ne4; }

        const int nsteps = tm;
        const int nfull  = nsteps >> 3;
        const int rem    = nsteps & 7;
        for (int c = 0; c < nfull; ++c) {
            #pragma unroll
            for (int j = 0; j < PF; ++j) STEP_F(j, ((j & 3) == 3))
            Pl += PF * RW; Pb += PF * RW;
        }
        #pragma unroll
        for (int j = 0; j < PF; ++j) { if (j < rem) STEP_F(j, 1) }
#undef STEP_F
    } else {
        // ================= BACKWARD: rows T_run-1 down to tm+1 =================
        const bool skipA = (z3 != z1);                               // 4l+1 -> 4l+3
        const bool skipB = (l < 31) && (y_true[b * Lsz + 2 * l + 2] != z3); // 4l+3 -> 4l+5
        float mz = 1.f; int ez;
        {   // init at t = T_run-1: indicator on states {2ll-1, 2ll}
            const int s0 = 4 * l, t1 = 2 * ll - 1, t2 = 2 * ll;
            e0 = (s0     == t1 || s0     == t2) ? 0 : ESENT;
            e1 = (s0 + 1 == t1 || s0 + 1 == t2) ? 0 : ESENT;
            e2 = (s0 + 2 == t1 || s0 + 2 == t2) ? 0 : ESENT;
            e3 = (s0 + 3 == t1 || s0 + 3 == t2) ? 0 : ESENT;
            ez = (ll == 64) ? 0 : ESENT;                  // state 128
        }
        #pragma unroll
        for (int i = 0; i < PF; ++i) {
            const int tt = Tlast - i;
            xr[i] = base[(size_t)tt * RW + l];
            pr[i] = __uint_as_float(base[(size_t)tt * RW + 32]);
        }
        const unsigned int* Pl = base + (size_t)(Tlast - 8) * RW + l;
        const float*        Pb = reinterpret_cast<const float*>(
                                     base + (size_t)(Tlast - 8) * RW + 32);

#define STEP_B(j, DN) {                                                       \
    const unsigned int u = xr[j];                                             \
    const float pbv = pr[j];                                                  \
    xr[j] = Pl[-((j) * RW)];                                                  \
    pr[j] = Pb[-((j) * RW)];                                                  \
    const float p1v = __int_as_float(u << 16);                                \
    const float p3v = __int_as_float(u & 0xFFFF0000u);                        \
    const float g0 = m0 * pbv, g1 = m1 * p1v, g2 = m2 * pbv, g3 = m3 * p3v;   \
    const float gz = mz * pbv;                                                \
    float gA = __shfl_down_sync(0xffffffffu, g0, 1);                          \
    int   eA = __shfl_down_sync(0xffffffffu, e0, 1);                          \
    float gB = __shfl_down_sync(0xffffffffu, g1, 1);                          \
    int   eB = __shfl_down_sync(0xffffffffu, e1, 1);                          \
    if (l == 31) { gA = gz; eA = ez; gB = 1.f; eB = ESENT; }                  \
    float nm0, nm1, nm2, nm3; int ne0, ne1, ne2, ne3;                         \
    { const int E = max(e0, e1);                                              \
      const float vv = fmaf(g1, wexp(e1 - E), g0 * wexp(e0 - E));             \
      NRM(vv, E, nm0, ne0, DN) }                                              \
    { const int ec = skipA ? e3 : ESENT;                                      \
      const int E = max(e1, max(e2, ec));                                     \
      float vv = fmaf(g2, wexp(e2 - E), g1 * wexp(e1 - E));                   \
      vv = fmaf(g3, wexp(ec - E), vv);                                        \
      NRM(vv, E, nm1, ne1, DN) }                                              \
    { const int E = max(e2, e3);                                              \
      const float vv = fmaf(g3, wexp(e3 - E), g2 * wexp(e2 - E));             \
      NRM(vv, E, nm2, ne2, DN) }                                              \
    { const int ec = skipB ? eB : ESENT;                                      \
      const int E = max(e3, max(eA, ec));                                     \
      float vv = fmaf(gA, wexp(eA - E), g3 * wexp(e3 - E));                   \
      vv = fmaf(gB, wexp(ec - E), vv);                                        \
      NRM(vv, E, nm3, ne3, DN) }                                              \
    { NRM(gz, ez, mz, ez, DN) }                                               \
    m0 = nm0; e0 = ne0; m1 = nm1; e1 = ne1;                                   \
    m2 = nm2; e2 = ne2; m3 = nm3; e3 = ne3; }

        const int nsteps = Tlast - tm;
        const int nfull  = nsteps >> 3;
        const int rem    = nsteps & 7;
        for (int c = 0; c < nfull; ++c) {
            #pragma unroll
            for (int j = 0; j < PF; ++j) STEP_B(j, ((j & 3) == 3))
            Pl -= PF * RW; Pb -= PF * RW;
        }
        #pragma unroll
        for (int j = 0; j < PF; ++j) { if (j < rem) STEP_B(j, 1) }
#undef STEP_B

        shB[row][4 * l + 0] = make_float2(m0, __int_as_float(e0));
        shB[row][4 * l + 1] = make_float2(m1, __int_as_float(e1));
        shB[row][4 * l + 2] = make_float2(m2, __int_as_float(e2));
        shB[row][4 * l + 3] = make_float2(m3, __int_as_float(e3));
        if (l == 0) shB[row][128] = make_float2(mz, __int_as_float(ez));
    }

    __syncthreads();

    if (dir == 0) {
        // combine: p = sum_s alpha_tm(s) * beta_tm(s)
        const float2 b0 = shB[row][4 * l + 0];
        const float2 b1 = shB[row][4 * l + 1];
        const float2 b2 = shB[row][4 * l + 2];
        const float2 b3 = shB[row][4 * l + 3];
        const float pm0 = m0 * b0.x; const int pe0 = e0 + __float_as_int(b0.y);
        const float pm1 = m1 * b1.x; const int pe1 = e1 + __float_as_int(b1.y);
        const float pm2 = m2 * b2.x; const int pe2 = e2 + __float_as_int(b2.y);
        const float pm3 = m3 * b3.x; const int pe3 = e3 + __float_as_int(b3.y);
        float pm4 = 0.f; int pe4 = 2 * ESENT;
        if (l == 31) {
            const float2 bz = shB[row][128];
            pm4 = m4 * bz.x; pe4 = e4 + __float_as_int(bz.y);
        }
        int E = max(max(pe0, pe1), max(pe2, max(pe3, pe4)));
        #pragma unroll
        for (int o = 16; o; o >>= 1) E = max(E, __shfl_xor_sync(0xffffffffu, E, o));
        float v = pm0 * wexp(pe0 - E) + pm1 * wexp(pe1 - E)
                + pm2 * wexp(pe2 - E) + pm3 * wexp(pe3 - E)
                + pm4 * wexp(pe4 - E);
        #pragma unroll
        for (int o = 16; o; o >>= 1) v += __shfl_xor_sync(0xffffffffu, v, o);
        if (l == 0) out[b] = -(__logf(v) + (float)E * LN2f);
    }
}

// ---------------------------------------------------------------------------
extern "C" void kernel_launch(void* const* d_in, const int* in_sizes, int n_in,
                              void* d_out, int out_size) {
    const int*   y_true = nullptr;
    const float* y_pred = nullptr;
    const int*   ilen   = nullptr;
    const int*   llen   = nullptr;
    for (int i = 0; i < n_in; ++i) {
        const int sz = in_sizes[i];
        if (sz == Bsz * Tsz * Csz)      y_pred = (const float*)d_in[i];
        else if (sz == Bsz * Lsz)       y_true = (const int*)d_in[i];
        else if (sz == Bsz) {
            if (!ilen) ilen = (const int*)d_in[i];
            else       llen = (const int*)d_in[i];
        }
    }
    float* out = (float*)d_out;

    ctc_probs<<<(Bsz * Tsz) / 4, 128>>>(y_pred, y_true, ilen);
    ctc_ab<<<Bsz / 2, 128>>>(y_true, ilen, llen, out);
}

// round 16
// speedup vs baseline: 1.4536x; 1.1728x over previous
#include <cuda_runtime.h>
#include <cuda_bf16.h>

#define Bsz   256
#define Tsz   512
#define Tpad  520
#define Csz   128
#define Lsz   64
#define BLANKC 127
#define PF    8
#define RW    34                 // row stride in u32 words (136 B)
#define LN2f  0.69314718055994530942f
#define ESENT (-(1 << 29))

// packed per-(b,t) row: words 0..31 = bf16x2(p_label(2l), p_label(2l+1));
// word 32 = f32 blank prob; word 33 = pad.
__device__ unsigned int g_pk[(size_t)Bsz * Tpad * RW];

// ---------------------------------------------------------------------------
// Kernel 1: softmax per (b,t) row; skip rows t >= input_length[b].
// ---------------------------------------------------------------------------
__global__ __launch_bounds__(128)
void ctc_probs(const float* __restrict__ y_pred,
               const int*   __restrict__ y_true,
               const int*   __restrict__ input_length) {
    const int row  = blockIdx.x * 4 + (threadIdx.x >> 5);   // row = b*512 + t
    const int lane = threadIdx.x & 31;
    const int wid  = (threadIdx.x >> 5);
    const int b = row >> 9;
    const int t = row & 511;
    if (t >= input_length[b]) return;                       // warp-uniform

    __shared__ __align__(16) float sh[4][128];

    const float4 v = reinterpret_cast<const float4*>(y_pred + (size_t)row * Csz)[lane];
    const float e0 = __expf(v.x), e1 = __expf(v.y),
                e2 = __expf(v.z), e3 = __expf(v.w);
    float esum = (e0 + e1) + (e2 + e3);
    #pragma unroll
    for (int o = 16; o; o >>= 1) esum += __shfl_xor_sync(0xffffffffu, esum, o);
    const float inv = __frcp_rn(esum);

    reinterpret_cast<float4*>(sh[wid])[lane] = make_float4(e0, e1, e2, e3);
    __syncwarp();

    const int* yt = y_true + b * Lsz;
    const float p1 = sh[wid][yt[2 * lane]]     * inv;
    const float p3 = sh[wid][yt[2 * lane + 1]] * inv;

    unsigned int* orow = g_pk + ((size_t)b * Tpad + t) * RW;
    const __nv_bfloat162 pk = __floats2bfloat162_rn(p1, p3);  // .x in low half
    orow[lane] = *reinterpret_cast<const unsigned int*>(&pk);
    if (lane == 0) orow[32] = __float_as_uint(sh[wid][BLANKC] * inv);
}

// 2^d, clamped to [-127, 126]; d <= -127 -> exactly 0.0f
__device__ __forceinline__ float wexp2(int d) {
    d = max(min(d, 126), -127);
    return __int_as_float(d * 8388608 + 0x3F800000);
}

// ---------------------------------------------------------------------------
// Kernel 2: fwd-bwd meet-in-the-middle, PER-LANE shared exponent.
// 2 rows/CTA, 4 warps = 1 chain per SMSP. Lane l owns states 4l..4l+3
// (fwd also 4l+4; bwd also scalar state 128). Mantissas carry within-lane
// spread (exact zeros for unreachable states); one int exponent E per lane.
// Cross-lane alignment = ONE constant power-of-2 weight per 4-step block.
// Inner step: pure FADD/FFMA/FMUL + shfl. Renorm every 4 steps.
// ---------------------------------------------------------------------------
__global__ __launch_bounds__(128)
void ctc_ab(const int* __restrict__ y_true,
            const int* __restrict__ input_length,
            const int* __restrict__ label_length,
            float*     __restrict__ out) {
    const int l   = threadIdx.x & 31;
    const int wid = threadIdx.x >> 5;
    const int row = wid >> 1;               // batch row within CTA
    const int dir = wid & 1;                // 0 = forward, 1 = backward
    const int b   = blockIdx.x * 2 + row;

    const int Trun  = input_length[b];
    const int Tlast = Trun - 1;
    const int tm    = Tlast >> 1;           // meeting time
    const int ll    = label_length[b];

    const int z1 = y_true[b * Lsz + 2 * l];
    const int z3 = y_true[b * Lsz + 2 * l + 1];
    const unsigned int* base = g_pk + (size_t)b * Tpad * RW;

    __shared__ __align__(16) float4 shBm[2][32];
    __shared__ __align__(16) int    shBE[2][32];
    __shared__ float shBz[2];

    float m0 = 0.f, m1 = 0.f, m2 = 0.f, m3 = 0.f, m4 = 0.f;
    int   E = 0;
    unsigned int xr[PF]; float pr[PF];

    if (dir == 0) {
        // ========================= FORWARD: t = 1..tm =========================
        const bool skip1 = (l > 0) && (z1 != y_true[b * Lsz + max(2 * l - 1, 0)]);
        const float s3w  = (z3 != z1) ? 1.f : 0.f;
        float wb0 = 0.f, wb1 = 0.f;

        if (l == 0) {                       // t=0 init (states 0,1)
            m0 = __uint_as_float(base[32]);
            m1 = __int_as_float(base[0] << 16);
        }

#define RENORM_F() {                                                          \
    const float M = fmaxf(fmaxf(m0, m1), fmaxf(fmaxf(m2, m3), m4));           \
    const int eloc = E + ((__float_as_int(M) >> 23) & 0xFF) - 127;            \
    const int elocN = __shfl_up_sync(0xffffffffu, eloc, 1);                   \
    const int Ef = max(eloc, elocN);                                          \
    const float sc = wexp2(E - Ef);                                           \
    m0 *= sc; m1 *= sc; m2 *= sc; m3 *= sc; m4 *= sc;                         \
    const int EfN = __shfl_up_sync(0xffffffffu, Ef, 1);                       \
    const float w = (l == 0) ? 0.f : wexp2(EfN - Ef);                         \
    wb0 = w; wb1 = skip1 ? w : 0.f;                                           \
    E = Ef; }

        RENORM_F()

        #pragma unroll
        for (int i = 0; i < PF; ++i) {
            xr[i] = base[(1 + i) * RW + l];
            pr[i] = __uint_as_float(base[(1 + i) * RW + 32]);
        }
        const unsigned int* Pl = base + 9 * RW + l;
        const float*        Pb = reinterpret_cast<const float*>(base + 9 * RW + 32);

#define STEP_F(j) {                                                           \
    const unsigned int u = xr[j];                                             \
    const float pbv = pr[j];                                                  \
    xr[j] = Pl[(j) * RW];                                                     \
    pr[j] = Pb[(j) * RW];                                                     \
    const float p1v = __int_as_float(u << 16);                                \
    const float p3v = __int_as_float(u & 0xFFFF0000u);                        \
    const float mN = __shfl_up_sync(0xffffffffu, m3, 1);                      \
    const float t01 = m0 + m1, t12 = m1 + m2;                                 \
    const float t23 = m2 + m3, t34 = m3 + m4;                                 \
    const float nm0 = fmaf(mN, wb0, m0) * pbv;                                \
    const float nm1 = fmaf(mN, wb1, t01) * p1v;                               \
    const float nm2 = t12 * pbv;                                              \
    const float nm3 = fmaf(m1, s3w, t23) * p3v;                               \
    const float nm4 = t34 * pbv;                                              \
    m0 = nm0; m1 = nm1; m2 = nm2; m3 = nm3; m4 = nm4; }

        const int nsteps = tm;
        const int nfull  = nsteps >> 3;
        const int rem    = nsteps & 7;
        for (int c = 0; c < nfull; ++c) {
            #pragma unroll
            for (int j = 0; j < PF; ++j) {
                STEP_F(j)
                if ((j & 3) == 3) RENORM_F()
            }
            Pl += PF * RW; Pb += PF * RW;
        }
        #pragma unroll
        for (int j = 0; j < PF; ++j) {
            if (j < rem) { STEP_F(j) RENORM_F() }
        }
#undef STEP_F
#undef RENORM_F
    } else {
        // ================= BACKWARD: rows T_run-1 down to tm+1 =================
        const float sAw  = (z3 != z1) ? 1.f : 0.f;                   // 4l+1 -> 4l+3
        const bool skipB = (l < 31) && (y_true[b * Lsz + 2 * l + 2] != z3);
        float mz = 0.f;
        float wbA = 0.f, wbB = 0.f;
        {   // init at t = T_run-1: indicator on states {2ll-1, 2ll}
            const int s0 = 4 * l, t1 = 2 * ll - 1, t2 = 2 * ll;
            m0 = (s0     == t1 || s0     == t2) ? 1.f : 0.f;
            m1 = (s0 + 1 == t1 || s0 + 1 == t2) ? 1.f : 0.f;
            m2 = (s0 + 2 == t1 || s0 + 2 == t2) ? 1.f : 0.f;
            m3 = (s0 + 3 == t1 || s0 + 3 == t2) ? 1.f : 0.f;
            mz = (ll == 64) ? 1.f : 0.f;                  // state 128
        }

#define RENORM_B() {                                                          \
    const float M = fmaxf(fmaxf(m0, m1), fmaxf(fmaxf(m2, m3), mz));           \
    const int eloc = E + ((__float_as_int(M) >> 23) & 0xFF) - 127;            \
    const int elocN = __shfl_down_sync(0xffffffffu, eloc, 1);                 \
    const int Ef = max(eloc, elocN);                                          \
    const float sc = wexp2(E - Ef);                                           \
    m0 *= sc; m1 *= sc; m2 *= sc; m3 *= sc; mz *= sc;                         \
    const int EfN = __shfl_down_sync(0xffffffffu, Ef, 1);                     \
    const float w = wexp2(EfN - Ef);                                          \
    wbA = (l == 31) ? 1.f : w;                                                \
    wbB = (skipB)   ? w   : 0.f;                                              \
    E = Ef; }

        RENORM_B()

        #pragma unroll
        for (int i = 0; i < PF; ++i) {
            const int tt = Tlast - i;
            xr[i] = base[(size_t)tt * RW + l];
            pr[i] = __uint_as_float(base[(size_t)tt * RW + 32]);
        }
        const unsigned int* Pl = base + (size_t)(Tlast - 8) * RW + l;
        const float*        Pb = reinterpret_cast<const float*>(
                                     base + (size_t)(Tlast - 8) * RW + 32);

#define STEP_B(j) {                                                           \
    const unsigned int u = xr[j];                                             \
    const float pbv = pr[j];                                                  \
    xr[j] = Pl[-((j) * RW)];                                                  \
    pr[j] = Pb[-((j) * RW)];                                                  \
    const float p1v = __int_as_float(u << 16);                                \
    const float p3v = __int_as_float(u & 0xFFFF0000u);                        \
    const float g0 = m0 * pbv, g1 = m1 * p1v;                                 \
    const float g2 = m2 * pbv, g3 = m3 * p3v;                                 \
    const float gz = mz * pbv;                                                \
    float gA = __shfl_down_sync(0xffffffffu, g0, 1);                          \
    float gB = __shfl_down_sync(0xffffffffu, g1, 1);                          \
    if (l == 31) { gA = gz; gB = 0.f; }                                       \
    const float nm0 = g0 + g1;                                                \
    const float nm1 = fmaf(g3, sAw, g1 + g2);                                 \
    const float nm2 = g2 + g3;                                                \
    const float nm3 = fmaf(gB, wbB, fmaf(gA, wbA, g3));                       \
    mz = gz; m0 = nm0; m1 = nm1; m2 = nm2; m3 = nm3; }

        const int nsteps = Tlast - tm;
        const int nfull  = nsteps >> 3;
        const int rem    = nsteps & 7;
        for (int c = 0; c < nfull; ++c) {
            #pragma unroll
            for (int j = 0; j < PF; ++j) {
                STEP_B(j)
                if ((j & 3) == 3) RENORM_B()
            }
            Pl -= PF * RW; Pb -= PF * RW;
        }
        #pragma unroll
        for (int j = 0; j < PF; ++j) {
            if (j < rem) { STEP_B(j) RENORM_B() }
        }
#undef STEP_B
#undef RENORM_B

        shBm[row][l] = make_float4(m0, m1, m2, m3);
        shBE[row][l] = E;
        if (l == 31) shBz[row] = mz;
    }

    __syncthreads();

    if (dir == 0) {
        // combine: p = sum_s alpha_tm(s) * beta_tm(s)
        const float4 bb = shBm[row][l];
        const int    Eb = shBE[row][l];
        float pm = (m0 * bb.x + m1 * bb.y) + (m2 * bb.z + m3 * bb.w);
        if (l == 31) pm = fmaf(m4, shBz[row], pm);
        int pe = (pm > 0.f) ? (E + Eb) : ESENT;   // mask dead lanes
        int Em = pe;
        #pragma unroll
        for (int o = 16; o; o >>= 1) Em = max(Em, __shfl_xor_sync(0xffffffffu, Em, o));
        float v = pm * wexp2(pe - Em);
        #pragma unroll
        for (int o = 16; o; o >>= 1) v += __shfl_xor_sync(0xffffffffu, v, o);
        if (l == 0) out[b] = -(__logf(v) + (float)Em * LN2f);
    }
}

// ---------------------------------------------------------------------------
extern "C" void kernel_launch(void* const* d_in, const int* in_sizes, int n_in,
                              void* d_out, int out_size) {
    const int*   y_true = nullptr;
    const float* y_pred = nullptr;
    const int*   ilen   = nullptr;
    const int*   llen   = nullptr;
    for (int i = 0; i < n_in; ++i) {
        const int sz = in_sizes[i];
        if (sz == Bsz * Tsz * Csz)      y_pred = (const float*)d_in[i];
        else if (sz == Bsz * Lsz)       y_true = (const int*)d_in[i];
        else if (sz == Bsz) {
            if (!ilen) ilen = (const int*)d_in[i];
            else       llen = (const int*)d_in[i];
        }
    }
    float* out = (float*)d_out;

    ctc_probs<<<(Bsz * Tsz) / 4, 128>>>(y_pred, y_true, ilen);
    ctc_ab<<<Bsz / 2, 128>>>(y_true, ilen, llen, out);
}